// round 17
// baseline (speedup 1.0000x reference)
#include <cuda_runtime.h>
#include <cuda_bf16.h>
#include <cstdint>

// Per-pixel dynamic 5x5 conv, channel-shared taps.
// x: [B=8, C=64, H=256, W=256] f32; w: [25, B, 1, H, W] f32
//
// PAIR-SPLIT QUADS: a 2x2 output quad is computed by TWO threads (lane L and
// L+16). A owns input rows 0-2 of the 6-row window, B rows 3-5; each holds 30
// tap-pairs (60 weight regs, one dummy zero row keeps warp code uniform).
// Partial sums are exchanged with one shfl.xor(16) pair per channel; A stores
// the top pixel row, B the bottom. Register/thread ~100 -> 5 CTAs/SM
// (20 warps, +67% TLP vs the 12-warp plateau). Warp-private 4-stage cp.async
// ring (6-row x 40-float slab), parity-split FFMA2/FFMA math, .cs stores.

#define BB 8
#define HW 65536
#define HH_DIM 256
#define WW_DIM 256
#define TW 32
#define TH 8                   // CTA tile rows
#define SMW 40                 // slab row stride (floats)
#define SROWS 6                // slab rows (2 out + 4 halo)
#define WSTAGE (SROWS * SMW)   // 240 floats = 960 B per stage
#define SLAB_B (WSTAGE * 4)
#define NSLOT4 60              // float4 slots per stage (6 x 10)
#define CPERCTA 32
#define NSTAGE 4
#define PFD 3

__device__ __forceinline__ void cp_async16(uint32_t saddr, const void* gaddr, int src_size) {
    asm volatile("cp.async.cg.shared.global [%0], [%1], 16, %2;"
                 :: "r"(saddr), "l"(gaddr), "r"(src_size));
}
__device__ __forceinline__ void cp_commit() {
    asm volatile("cp.async.commit_group;");
}
template <int N>
__device__ __forceinline__ void cp_wait() {
    asm volatile("cp.async.wait_group %0;" :: "n"(N));
}

__device__ __forceinline__ uint64_t lds64(uint32_t a) {
    uint64_t v; asm volatile("ld.shared.b64 %0, [%1];" : "=l"(v) : "r"(a)); return v;
}
__device__ __forceinline__ void ffma2(uint64_t& d, uint64_t a, uint64_t b) {
    asm("fma.rn.f32x2 %0, %1, %2, %0;" : "+l"(d) : "l"(a), "l"(b));
}
__device__ __forceinline__ void unpack2f(uint64_t v, float& lo, float& hi) {
    asm("mov.b64 {%0, %1}, %2;" : "=f"(lo), "=f"(hi) : "l"(v));
}
__device__ __forceinline__ float lo_f(uint64_t v) { float a, b; unpack2f(v, a, b); return a; }
__device__ __forceinline__ float hi_f(uint64_t v) { float a, b; unpack2f(v, a, b); return b; }
__device__ __forceinline__ void stcs2(float* p, float a, float b) {
    asm volatile("st.global.cs.v2.f32 [%0], {%1, %2};" :: "l"(p), "f"(a), "f"(b) : "memory");
}

__global__ __launch_bounds__(128, 5)
void dynconv5x5_kernel(const float* __restrict__ x,
                       const float* __restrict__ wgt,
                       float* __restrict__ out) {
    __shared__ float sm[4][NSTAGE][WSTAGE];   // 15.36 KB: [warp][stage][slab]

    const int tid  = threadIdx.x;
    const int wid  = tid >> 5;
    const int lane = tid & 31;
    const int q    = lane & 15;     // quad column (16 quads per warp row)
    const int half = lane >> 4;     // 0 = rows 0-2 ("A"), 1 = rows 3-5 ("B")
    const int w0   = blockIdx.x * TW;
    const int h0   = blockIdx.y * TH;
    const int z    = blockIdx.z;
    const int b    = z >> 1;
    const int c0   = (z & 1) * CPERCTA;

    const int oh    = h0 + wid * 2;     // quad top pixel row (warp owns 1 quad-row)
    const int ow    = w0 + q * 2;
    const int slab0 = oh - 2;           // first input row staged in the slab

    // ---- weights: 30 tap-pairs = 60 regs (dummy zero row keeps code uniform)
    // local row i (0..2) <-> slab row half*3+i <-> image row oh-2+half*3+i
    // top px weight row  rt = half*3 + i        (invalid for B,i=2 -> zero)
    // bot px weight row  rb = rt - 1            (invalid for A,i=0 -> zero)
    uint64_t wTp[9], wBp[9];
    float wTsl[6], wTsh[6], wBsl[6], wBsh[6];
    {
        const int base = half * 3;
#pragma unroll
        for (int i = 0; i < 3; i++) {
            int rt = base + i;
            int rb = rt - 1;
            bool vt = (rt <= 4);
            bool vb = (rb >= 0);
            int rtc = vt ? rt : 0;     // clamped (always-legal address)
            int rbc = vb ? rb : 0;
#pragma unroll
            for (int ww = 0; ww < 5; ww++) {
                const float* pt = &wgt[(((size_t)(rtc * 5 + ww) * BB + b) * HH_DIM + oh) * WW_DIM + ow];
                const float* pb = &wgt[(((size_t)(rbc * 5 + ww) * BB + b) * HH_DIM + (oh + 1)) * WW_DIM + ow];
                uint64_t t  = vt ? *(const uint64_t*)pt : 0ull;
                uint64_t bo = vb ? *(const uint64_t*)pb : 0ull;
                if ((ww & 1) == 0) {
                    wTp[i * 3 + ww / 2] = t;
                    wBp[i * 3 + ww / 2] = bo;
                } else {
                    int j = i * 2 + (ww == 3);
                    unpack2f(t,  wTsl[j], wTsh[j]);
                    unpack2f(bo, wBsl[j], wBsh[j]);
                }
            }
        }
    }

    // ---- 16B staging slots: 60 float4 = 6 rows x 10; col c <-> gw w0-4+c
    int xoff[2];
    int ssz [2];
    int soff[2];
    const bool has2 = (lane < NSLOT4 - 32);   // lane < 28
#pragma unroll
    for (int j = 0; j < 2; j++) {
        int i    = lane + j * 32;
        int r    = i / 10;
        int col4 = i - r * 10;
        int gh = slab0 + r;
        int gw = w0 - 4 + col4 * 4;
        bool v = (i < NSLOT4) && gh >= 0 && gh < HH_DIM && gw >= 0 && gw < WW_DIM;
        xoff[j] = gh * WW_DIM + gw;
        ssz[j]  = v ? 16 : 0;
        soff[j] = (r * SMW + col4 * 4) * 4;
    }

    const float* xc = x + ((size_t)b * 64 + c0) * HW;
    // this thread stores pixel row oh+half
    float* op = out + (((size_t)b * 64 + c0) * HW) + (oh + half) * WW_DIM + ow;

    const uint32_t wbase = (uint32_t)__cvta_generic_to_shared(&sm[wid][0][0]);
    // compute base: my 3 slab rows start at row half*3; x0 lives at col q*2+2
    const uint32_t cbase = wbase + ((half * 3) * SMW + (q * 2 + 2)) * 4;

    // ---- prologue: stage channels 0..PFD-1
#pragma unroll
    for (int p = 0; p < PFD; p++) {
        const float* xp = xc + (size_t)p * HW;
        const uint32_t sp = wbase + p * SLAB_B;
        cp_async16(sp + soff[0], xp + xoff[0], ssz[0]);
        if (has2) cp_async16(sp + soff[1], xp + xoff[1], ssz[1]);
        cp_commit();
    }

#pragma unroll 4
    for (int c = 0; c < CPERCTA; c++) {
        if (c + PFD < CPERCTA) cp_wait<PFD - 1>(); else cp_wait<0>();
        __syncwarp(0xffffffffu);

        const uint32_t sbase = cbase + (c & (NSTAGE - 1)) * SLAB_B;

        uint64_t aT = 0, aB = 0;
        float aTs0 = 0.f, aTs1 = 0.f, aBs0 = 0.f, aBs1 = 0.f;
#pragma unroll
        for (int i = 0; i < 3; i++) {
            uint32_t a = sbase + i * (SMW * 4);
            uint64_t p0 = lds64(a);        // {x0,x1}
            uint64_t p2 = lds64(a + 8);    // {x2,x3}
            uint64_t p4 = lds64(a + 16);   // {x4,x5}
            float x1 = hi_f(p0);
            float x2 = lo_f(p2);
            float x3 = hi_f(p2);
            float x4 = lo_f(p4);

            ffma2(aT, p0, wTp[i * 3 + 0]);
            ffma2(aT, p2, wTp[i * 3 + 1]);
            ffma2(aT, p4, wTp[i * 3 + 2]);
            aTs0 = fmaf(x1, wTsl[i * 2 + 0], aTs0);
            aTs1 = fmaf(x2, wTsh[i * 2 + 0], aTs1);
            aTs0 = fmaf(x3, wTsl[i * 2 + 1], aTs0);
            aTs1 = fmaf(x4, wTsh[i * 2 + 1], aTs1);

            ffma2(aB, p0, wBp[i * 3 + 0]);
            ffma2(aB, p2, wBp[i * 3 + 1]);
            ffma2(aB, p4, wBp[i * 3 + 2]);
            aBs0 = fmaf(x1, wBsl[i * 2 + 0], aBs0);
            aBs1 = fmaf(x2, wBsh[i * 2 + 0], aBs1);
            aBs0 = fmaf(x3, wBsl[i * 2 + 1], aBs0);
            aBs1 = fmaf(x4, wBsh[i * 2 + 1], aBs1);
        }

        // merge packed+scalar chains into per-pixel-row partials
        float l, h;
        unpack2f(aT, l, h);
        float t0 = l + aTs0, t1 = h + aTs1;   // my partial for TOP pixel row
        unpack2f(aB, l, h);
        float b0 = l + aBs0, b1 = h + aBs1;   // my partial for BOTTOM pixel row

        // exchange with partner lane (L <-> L+16): send the half I don't store
        float s0 = half ? t0 : b0;
        float s1 = half ? t1 : b1;
        float r0 = __shfl_xor_sync(0xffffffffu, s0, 16);
        float r1 = __shfl_xor_sync(0xffffffffu, s1, 16);
        float k0 = half ? b0 : t0;
        float k1 = half ? b1 : t1;

        stcs2(op + (size_t)c * HW, k0 + r0, k1 + r1);

        // stage channel c+PFD into its ring slot
        if (c + PFD < CPERCTA) {
            const float* xs = xc + (size_t)(c + PFD) * HW;
            const uint32_t sp = wbase + ((c + PFD) & (NSTAGE - 1)) * SLAB_B;
            cp_async16(sp + soff[0], xs + xoff[0], ssz[0]);
            if (has2) cp_async16(sp + soff[1], xs + xoff[1], ssz[1]);
            cp_commit();
        }
    }
}

extern "C" void kernel_launch(void* const* d_in, const int* in_sizes, int n_in,
                              void* d_out, int out_size) {
    const float* x   = (const float*)d_in[0];
    const float* wgt = (const float*)d_in[1];
    float*       out = (float*)d_out;

    dim3 grid(WW_DIM / TW, HH_DIM / TH, BB * 2);   // 8 x 32 x 16 = 4096 blocks
    dim3 block(128);
    dynconv5x5_kernel<<<grid, block>>>(x, wgt, out);
}